// round 12
// baseline (speedup 1.0000x reference)
#include <cuda_runtime.h>
#include <math.h>

typedef unsigned long long ull;

// SpatialGRU B=64,C=16,L=R=64,U=64,K=208. Persistent row-pipelined kernel.
// Round-12 = Round-11 + (1) W1 pre-duplicated {w,w} float2 in global ->
// GEMM1 loads LDG.64 directly, deleting 12 mov.b64 per k per SMSP (~1.2K
// cyc/cell), + (2) epilogue softmax without max-shift (z-diffs are O(1),
// e0==1), deleting 1 exp + 3 fmax per h-value. No other changes.

#define KDIM 208
#define N1   384
#define JT   6
#define RS2  10     // float2 per As row (80 B)

// smem float offsets
#define P_OFF    0          // [4 kg][6 j][8 mp][64 nl] float2 = 24576 floats
#define W2S_OFF  24576      // 208*64 = 13312
#define AS_OFF   37888      // float2[208][RS2] = 4160 floats
#define HE_OFF   42048      // [2][16][64] = 2048
#define HO_OFF   44096      // 2048
#define HT_OFF   46144      // 2048
#define YP_OFF   48192      // [3][16][64] = 3072
#define B1_OFF   51264      // 384
#define WIJB_OFF 51648      // 64
#define SMEM_FLOATS 51712
#define SMEM_BYTES (SMEM_FLOATS*4)

__device__ float  g_H[64 * 64 * 64 * 64];  // [(l*64+r)][b][u]; only odd l used
__device__ float2 g_Xp[4096 * 4 * 128];    // [(l*64+r)][q][c][mp] m-paired x
__device__ float2 g_Wt1[208 * 384];        // [k][n] duplicated {w,w}; n<192 wr, else wz-diff
__device__ float  g_Wt2[208 * 64];         // [k][n] k<192: U_w ; else wij
__device__ int    g_flag[4 * 64 * 64];     // [q][row][r]

#define FMA2(acc, a, b) asm("fma.rn.f32x2 %0, %1, %2, %0;" : "+l"(acc) : "l"(a), "l"(b))

__device__ __forceinline__ ull dup2(float w) {
    unsigned int wi = __float_as_uint(w);
    ull d;
    asm("mov.b64 %0, {%1,%2};" : "=l"(d) : "r"(wi), "r"(wi));
    return d;
}
__device__ __forceinline__ float2 unpack2(ull v) {
    unsigned int a, b;
    asm("mov.b64 {%0,%1}, %2;" : "=r"(a), "=r"(b) : "l"(v));
    return make_float2(__uint_as_float(a), __uint_as_float(b));
}
__device__ __forceinline__ float fast_tanh(float x) {
    x = fminf(fmaxf(x, -15.0f), 15.0f);
    float e = __expf(2.0f * x);
    return __fdividef(e - 1.0f, e + 1.0f);
}

extern "C" __global__ void init_kernel(const float* __restrict__ inputs,
                                       const float* __restrict__ wr_w,
                                       const float* __restrict__ wz_w,
                                       const float* __restrict__ U_w,
                                       const float* __restrict__ wij_w)
{
    int t = blockIdx.x * blockDim.x + threadIdx.x;
    int stride = gridDim.x * blockDim.x;
    for (int i = t; i < 4 * 64 * 64; i += stride) g_flag[i] = 0;
    for (int i = t; i < 4096 * 4 * 128; i += stride) {
        int mp = i & 7, c = (i >> 3) & 15, q = (i >> 7) & 3, cell = i >> 9;
        int l = cell >> 6, r = cell & 63, b = q * 16 + 2 * mp;
        float v0 = inputs[((b * 16 + c) * 64 + l) * 64 + r];
        float v1 = inputs[(((b + 1) * 16 + c) * 64 + l) * 64 + r];
        g_Xp[i] = make_float2(v0, v1);
    }
    for (int i = t; i < 208 * 384; i += stride) {
        int k = i / 384, n = i - k * 384;
        float w;
        if (n < 192) w = wr_w[n * KDIM + k];
        else { int tt = n - 192, g = tt >> 6, u = tt & 63;
               w = wz_w[(64 * (g + 1) + u) * KDIM + k] - wz_w[u * KDIM + k]; }
        g_Wt1[i] = make_float2(w, w);
    }
    for (int i = t; i < 208 * 64; i += stride) {
        int k = i >> 6, n = i & 63;
        g_Wt2[i] = (k < 192) ? U_w[n * 192 + k] : wij_w[n * 16 + (k - 192)];
    }
}

extern __shared__ float smem[];

#define LDW1(dst, KK) { const ull* _b = wp + (size_t)(KK) * N1; \
    _Pragma("unroll") for (int _j = 0; _j < JT; _j++) dst[_j] = _b[_j * 64]; }
#define LDA(dst, KK) { const ulonglong2* _r = Ab + (KK) * 5; \
    dst[0] = _r[0]; dst[1] = _r[1]; dst[2] = _r[2]; dst[3] = _r[3]; }
#define FMAB(WD, A) { _Pragma("unroll") for (int _j = 0; _j < JT; _j++) { \
    FMA2(acc[_j][0], A[0].x, WD[_j]); FMA2(acc[_j][1], A[0].y, WD[_j]); \
    FMA2(acc[_j][2], A[1].x, WD[_j]); FMA2(acc[_j][3], A[1].y, WD[_j]); \
    FMA2(acc[_j][4], A[2].x, WD[_j]); FMA2(acc[_j][5], A[2].y, WD[_j]); \
    FMA2(acc[_j][6], A[3].x, WD[_j]); FMA2(acc[_j][7], A[3].y, WD[_j]); } }

extern "C" __global__ void __launch_bounds__(256, 1)
pipeline_kernel(const float* __restrict__ wr_b, const float* __restrict__ wz_b,
                const float* __restrict__ wij_b, float* __restrict__ out)
{
    const int tid = threadIdx.x;
    const int p = blockIdx.x >> 2;     // row pair 0..31
    const int q = blockIdx.x & 3;      // batch quarter
    const int b0 = q * 16;
    const int nl = tid & 63;           // n-lane
    const int kg = tid >> 6;           // k-group (52 k each)
    const int mp_b = tid >> 5;         // build-phase m-pair 0..7
    const int kb_b = tid & 31;

    float2* Pv    = (float2*)(smem + P_OFF);
    float*  ws2   = smem + W2S_OFF;
    float2* As    = (float2*)(smem + AS_OFF);
    float*  He    = smem + HE_OFF;
    float*  Ho    = smem + HO_OFF;
    float*  Ht    = smem + HT_OFF;
    float*  Yp    = smem + YP_OFF;
    float*  bias1 = smem + B1_OFF;
    float*  wijb  = smem + WIJB_OFF;

    // one-time preload
    for (int i = tid; i < 208 * 64; i += 256) ws2[i] = g_Wt2[i];
    for (int i = tid; i < 384; i += 256) {
        float b;
        if (i < 192) b = wr_b[i];
        else { int tt = i - 192, g = tt >> 6, u = tt & 63;
               b = wz_b[64 * (g + 1) + u] - wz_b[u]; }
        bias1[i] = b;
    }
    if (tid < 64) wijb[tid] = wij_b[tid];
    for (int i = tid; i < 6144; i += 256) He[i] = 0.0f;   // He,Ho,Ht contiguous
    {   // x-section of As for s=0: cell (2p, 0)
        const float2* Xp0 = g_Xp + ((size_t)((2 * p) * 64 + 0) * 4 + q) * 128;
        if (tid < 128) As[(192 + (tid >> 3)) * RS2 + (tid & 7)] = Xp0[tid];
    }
    __syncthreads();

    const ull*   wp  = (const ull*)g_Wt1 + (size_t)(kg * 52) * N1 + nl;
    const float* Wb2 = ws2 + (size_t)(kg * 52) * 64 + nl;
    const ulonglong2* Ab = (const ulonglong2*)As + (size_t)(kg * 52) * 5;

    for (int s = 0; s < 128; s++) {
        const int sub = s & 1;
        const int r = s >> 1;
        const int l = 2 * p + sub;
        const int rb = r & 1, rp = rb ^ 1;

        const float *hl_s, *ht_s, *hd_s;
        float* hdst;
        if (sub == 0) { hl_s = He + rp * 1024; ht_s = Ht + rb * 1024;
                        hd_s = Ht + rp * 1024; hdst = He + rb * 1024; }
        else          { hl_s = Ho + rp * 1024; ht_s = He + rb * 1024;
                        hd_s = He + rp * 1024; hdst = Ho + rb * 1024; }

        if (sub == 0 && p > 0) {
            if (tid == 0) {
                const int* fp = &g_flag[(q * 64 + (2 * p - 1)) * 64 + r];
                int v;
                do {
                    asm volatile("ld.acquire.gpu.global.b32 %0, [%1];" : "=r"(v) : "l"(fp));
                    if (!v) __nanosleep(64);
                } while (!v);
            }
            __syncthreads();
        }

        const float* Gtop = g_H + ((size_t)((2 * p - 1) * 64 + r)) * 4096 + b0 * 64;
        float* Htcur = Ht + rb * 1024;

        // ---- build A1 h-rows [k<192]: m-paired {h_top|h_left|h_diag} ----
        {
            const int m0 = 2 * mp_b, m1 = m0 + 1;
#pragma unroll
            for (int c = 0; c < 6; c++) {
                int k = kb_b + 32 * c;
                float v0, v1;
                if (k < 64) {
                    if (sub == 0) {
                        if (p > 0) {
                            v0 = Gtop[m0 * 64 + k]; v1 = Gtop[m1 * 64 + k];
                            Htcur[m0 * 64 + k] = v0; Htcur[m1 * 64 + k] = v1;
                        } else { v0 = 0.0f; v1 = 0.0f; }
                    } else {
                        v0 = ht_s[m0 * 64 + k]; v1 = ht_s[m1 * 64 + k];
                    }
                } else if (k < 128) {
                    int ko = k - 64;
                    v0 = hl_s[m0 * 64 + ko]; v1 = hl_s[m1 * 64 + ko];
                } else {
                    int ko = k - 128;
                    v0 = hd_s[m0 * 64 + ko]; v1 = hd_s[m1 * 64 + ko];
                }
                As[k * RS2 + mp_b] = make_float2(v0, v1);
            }
        }
        // hoisted stage-1 W prologue (pre-duplicated LDG.64)
        ull wA[JT], wB[JT];
        LDW1(wA, 0); LDW1(wB, 1);
        __syncthreads();

        // ---- stage-1 GEMM: acc[j][mp], W from L2 (4-deep), A broadcast ----
        ull acc[JT][8];
#pragma unroll
        for (int j = 0; j < JT; j++)
#pragma unroll
            for (int m = 0; m < 8; m++) acc[j][m] = 0ULL;
        {
            ulonglong2 aA[4], aB[4];
            LDA(aA, 0);
            for (int kk = 0; kk < 52; kk += 2) {
                LDA(aB, kk + 1);
                FMAB(wA, aA);
                if (kk + 2 < 52) LDW1(wA, kk + 2);
                if (kk + 2 < 52) LDA(aA, kk + 2);
                FMAB(wB, aB);
                if (kk + 3 < 52) LDW1(wB, kk + 3);
            }
        }
#pragma unroll
        for (int j = 0; j < JT; j++)
#pragma unroll
            for (int m = 0; m < 8; m++)
                Pv[(size_t)kg * 3072 + (j * 8 + m) * 64 + nl] = unpack2(acc[j][m]);
        __syncthreads();

        // ---- reduce1 (fused build-A2): rr -> As = rr*hu ; z-diff -> Yp ----
#pragma unroll
        for (int i = 0; i < 12; i++) {
            int f = tid + 256 * i;
            int nl2 = f & 63, m = (f >> 6) & 7, j = f >> 9;
            int base = (j * 8 + m) * 64 + nl2;
            float2 s0 = Pv[base], s1 = Pv[3072 + base];
            float2 s2 = Pv[6144 + base], s3 = Pv[9216 + base];
            int n = nl2 + 64 * j;
            float b = bias1[n];
            float x0 = ((s0.x + s1.x) + (s2.x + s3.x)) + b;
            float x1 = ((s0.y + s1.y) + (s2.y + s3.y)) + b;
            if (j < 3) {
                x0 = __fdividef(1.0f, 1.0f + __expf(-x0));
                x1 = __fdividef(1.0f, 1.0f + __expf(-x1));
                // A2 k-order: [h_left | h_top | h_diag]
                const float* Hs = (j == 0) ? hl_s : ((j == 1) ? ht_s : hd_s);
                float h0 = Hs[(2 * m) * 64 + nl2];
                float h1 = Hs[(2 * m + 1) * 64 + nl2];
                As[n * RS2 + m] = make_float2(x0 * h0, x1 * h1);
            } else {
                int g = j - 3;
                Yp[g * 1024 + (2 * m) * 64 + nl2] = x0;
                Yp[g * 1024 + (2 * m + 1) * 64 + nl2] = x1;
            }
        }
        // hoisted stage-2 W prologue (smem)
        float w4[4];
#pragma unroll
        for (int i = 0; i < 4; i++) w4[i] = Wb2[i * 64];
        __syncthreads();

        // ---- stage-2 GEMM: A = As, W2 from smem ----
        ull acc2[8];
#pragma unroll
        for (int m = 0; m < 8; m++) acc2[m] = 0ULL;
        {
#pragma unroll 4
            for (int kk = 0; kk < 52; kk++) {
                ulonglong2 a[4];
                LDA(a, kk);
                ull wd = dup2(w4[kk & 3]);
                if (kk + 4 < 52) w4[kk & 3] = Wb2[(kk + 4) * 64];
                FMA2(acc2[0], a[0].x, wd); FMA2(acc2[1], a[0].y, wd);
                FMA2(acc2[2], a[1].x, wd); FMA2(acc2[3], a[1].y, wd);
                FMA2(acc2[4], a[2].x, wd); FMA2(acc2[5], a[2].y, wd);
                FMA2(acc2[6], a[3].x, wd); FMA2(acc2[7], a[3].y, wd);
            }
        }
#pragma unroll
        for (int m = 0; m < 8; m++)
            Pv[(size_t)kg * 512 + m * 64 + nl] = unpack2(acc2[m]);
        __syncthreads();

        // ---- epilogue: reduce + tanh + gates (no max-shift) + H update ----
        {
            float* Gout = g_H + ((size_t)(l * 64 + r)) * 4096 + b0 * 64;
            const bool last = (l == 63) && (r == 63);
#pragma unroll
            for (int i = 0; i < 2; i++) {
                int f = tid + 256 * i;
                int u = f & 63, m = f >> 6;
                int base = m * 64 + u;
                float2 s0 = Pv[base], s1 = Pv[512 + base];
                float2 s2 = Pv[1024 + base], s3 = Pv[1536 + base];
                float wb = wijb[u];
                float av[2] = {((s0.x + s1.x) + (s2.x + s3.x)) + wb,
                               ((s0.y + s1.y) + (s2.y + s3.y)) + wb};
#pragma unroll
                for (int h2 = 0; h2 < 2; h2++) {
                    int mm = 2 * m + h2;
                    float hnew = fast_tanh(av[h2]);
                    float z1 = Yp[mm * 64 + u];
                    float z2 = Yp[1024 + mm * 64 + u];
                    float z3 = Yp[2048 + mm * 64 + u];
                    float e1 = __expf(z1), e2 = __expf(z2), e3 = __expf(z3);
                    float inv = __fdividef(1.0f, 1.0f + e1 + e2 + e3);
                    float h = (hnew + e1 * hl_s[mm * 64 + u] +
                               e2 * ht_s[mm * 64 + u] + e3 * hd_s[mm * 64 + u]) * inv;
                    hdst[mm * 64 + u] = h;
                    if (sub == 1) Gout[mm * 64 + u] = h;
                    if (last) out[(b0 + mm) * 64 + u] = h;
                }
            }
            if (s < 127 && tid < 128) {   // x-section of As for next cell
                int s2_ = s + 1;
                int r2 = s2_ >> 1, l2 = 2 * p + (s2_ & 1);
                const float2* Xpn = g_Xp + ((size_t)(l2 * 64 + r2) * 4 + q) * 128;
                As[(192 + (tid >> 3)) * RS2 + (tid & 7)] = Xpn[tid];
            }
        }
        __syncthreads();

        if (sub == 1 && tid == 0) {
            __threadfence();
            int* fp = &g_flag[(q * 64 + l) * 64 + r];
            asm volatile("st.release.gpu.global.b32 [%0], %1;" :: "l"(fp), "r"(1) : "memory");
        }
    }
}

extern "C" void kernel_launch(void* const* d_in, const int* in_sizes, int n_in,
                              void* d_out, int out_size)
{
    const float* inputs = (const float*)d_in[0];
    const float* wr_w   = (const float*)d_in[1];
    const float* wr_b   = (const float*)d_in[2];
    const float* wz_w   = (const float*)d_in[3];
    const float* wz_b   = (const float*)d_in[4];
    const float* wij_w  = (const float*)d_in[5];
    const float* wij_b  = (const float*)d_in[6];
    const float* U_w    = (const float*)d_in[7];
    float* out = (float*)d_out;

    cudaFuncSetAttribute(pipeline_kernel, cudaFuncAttributeMaxDynamicSharedMemorySize, SMEM_BYTES);

    init_kernel<<<512, 256>>>(inputs, wr_w, wz_w, U_w, wij_w);
    pipeline_kernel<<<128, 256, SMEM_BYTES>>>(wr_b, wz_b, wij_b, out);
}

// round 13
// speedup vs baseline: 1.2306x; 1.2306x over previous
#include <cuda_runtime.h>
#include <math.h>

typedef unsigned long long ull;

// SpatialGRU B=64,C=16,L=R=64,U=64,K=208. Persistent row-pipelined kernel.
// Round-13 = Round-11 (best) + epilogue softmax without max-shift +
// GEMM2 explicit 4-slot W rotation (no kk&3 alu) + redundant threadfence
// removed before st.release. GEMM1/W1 path identical to Round-11.

#define KDIM 208
#define N1   384
#define JT   6
#define RS2  10     // float2 per As row (80 B)

// smem float offsets
#define P_OFF    0          // [4 kg][6 j][8 mp][64 nl] float2 = 24576 floats
#define W2S_OFF  24576      // 208*64 = 13312
#define AS_OFF   37888      // float2[208][RS2] = 4160 floats
#define HE_OFF   42048      // [2][16][64] = 2048
#define HO_OFF   44096      // 2048
#define HT_OFF   46144      // 2048
#define YP_OFF   48192      // [3][16][64] = 3072
#define B1_OFF   51264      // 384
#define WIJB_OFF 51648      // 64
#define SMEM_FLOATS 51712
#define SMEM_BYTES (SMEM_FLOATS*4)

__device__ float  g_H[64 * 64 * 64 * 64];  // [(l*64+r)][b][u]; only odd l used
__device__ float2 g_Xp[4096 * 4 * 128];    // [(l*64+r)][q][c][mp] m-paired x
__device__ float  g_Wt1[208 * 384];        // [k][n] n<192: wr ; n>=192: wz-diff
__device__ float  g_Wt2[208 * 64];         // [k][n] k<192: U_w ; else wij
__device__ int    g_flag[4 * 64 * 64];     // [q][row][r]

#define FMA2(acc, a, b) asm("fma.rn.f32x2 %0, %1, %2, %0;" : "+l"(acc) : "l"(a), "l"(b))

__device__ __forceinline__ ull dup2(float w) {
    unsigned int wi = __float_as_uint(w);
    ull d;
    asm("mov.b64 %0, {%1,%2};" : "=l"(d) : "r"(wi), "r"(wi));
    return d;
}
__device__ __forceinline__ float2 unpack2(ull v) {
    unsigned int a, b;
    asm("mov.b64 {%0,%1}, %2;" : "=r"(a), "=r"(b) : "l"(v));
    return make_float2(__uint_as_float(a), __uint_as_float(b));
}
__device__ __forceinline__ float fast_tanh(float x) {
    x = fminf(fmaxf(x, -15.0f), 15.0f);
    float e = __expf(2.0f * x);
    return __fdividef(e - 1.0f, e + 1.0f);
}

extern "C" __global__ void init_kernel(const float* __restrict__ inputs,
                                       const float* __restrict__ wr_w,
                                       const float* __restrict__ wz_w,
                                       const float* __restrict__ U_w,
                                       const float* __restrict__ wij_w)
{
    int t = blockIdx.x * blockDim.x + threadIdx.x;
    int stride = gridDim.x * blockDim.x;
    for (int i = t; i < 4 * 64 * 64; i += stride) g_flag[i] = 0;
    for (int i = t; i < 4096 * 4 * 128; i += stride) {
        int mp = i & 7, c = (i >> 3) & 15, q = (i >> 7) & 3, cell = i >> 9;
        int l = cell >> 6, r = cell & 63, b = q * 16 + 2 * mp;
        float v0 = inputs[((b * 16 + c) * 64 + l) * 64 + r];
        float v1 = inputs[(((b + 1) * 16 + c) * 64 + l) * 64 + r];
        g_Xp[i] = make_float2(v0, v1);
    }
    for (int i = t; i < 208 * 384; i += stride) {
        int k = i / 384, n = i - k * 384;
        float w;
        if (n < 192) w = wr_w[n * KDIM + k];
        else { int tt = n - 192, g = tt >> 6, u = tt & 63;
               w = wz_w[(64 * (g + 1) + u) * KDIM + k] - wz_w[u * KDIM + k]; }
        g_Wt1[i] = w;
    }
    for (int i = t; i < 208 * 64; i += stride) {
        int k = i >> 6, n = i & 63;
        g_Wt2[i] = (k < 192) ? U_w[n * 192 + k] : wij_w[n * 16 + (k - 192)];
    }
}

extern __shared__ float smem[];

#define LDW1(dst, KK) { const float* _b = wp + (size_t)(KK) * N1; \
    _Pragma("unroll") for (int _j = 0; _j < JT; _j++) dst[_j] = _b[_j * 64]; }
#define LDA(dst, KK) { const ulonglong2* _r = Ab + (KK) * 5; \
    dst[0] = _r[0]; dst[1] = _r[1]; dst[2] = _r[2]; dst[3] = _r[3]; }
#define FMAB(WD, A) { _Pragma("unroll") for (int _j = 0; _j < JT; _j++) { \
    FMA2(acc[_j][0], A[0].x, WD[_j]); FMA2(acc[_j][1], A[0].y, WD[_j]); \
    FMA2(acc[_j][2], A[1].x, WD[_j]); FMA2(acc[_j][3], A[1].y, WD[_j]); \
    FMA2(acc[_j][4], A[2].x, WD[_j]); FMA2(acc[_j][5], A[2].y, WD[_j]); \
    FMA2(acc[_j][6], A[3].x, WD[_j]); FMA2(acc[_j][7], A[3].y, WD[_j]); } }

// one GEMM2 k-step with weight slot WREG; reloads WREG 4 steps ahead
#define G2STEP(WREG, KK) { \
    ulonglong2 a[4]; \
    LDA(a, KK); \
    ull wd = dup2(WREG); \
    if ((KK) + 4 < 52) WREG = Wb2[((KK) + 4) * 64]; \
    FMA2(acc2[0], a[0].x, wd); FMA2(acc2[1], a[0].y, wd); \
    FMA2(acc2[2], a[1].x, wd); FMA2(acc2[3], a[1].y, wd); \
    FMA2(acc2[4], a[2].x, wd); FMA2(acc2[5], a[2].y, wd); \
    FMA2(acc2[6], a[3].x, wd); FMA2(acc2[7], a[3].y, wd); }

extern "C" __global__ void __launch_bounds__(256, 1)
pipeline_kernel(const float* __restrict__ wr_b, const float* __restrict__ wz_b,
                const float* __restrict__ wij_b, float* __restrict__ out)
{
    const int tid = threadIdx.x;
    const int p = blockIdx.x >> 2;     // row pair 0..31
    const int q = blockIdx.x & 3;      // batch quarter
    const int b0 = q * 16;
    const int nl = tid & 63;           // n-lane
    const int kg = tid >> 6;           // k-group (52 k each)
    const int mp_b = tid >> 5;         // build-phase m-pair 0..7
    const int kb_b = tid & 31;

    float2* Pv    = (float2*)(smem + P_OFF);
    float*  ws2   = smem + W2S_OFF;
    float2* As    = (float2*)(smem + AS_OFF);
    float*  He    = smem + HE_OFF;
    float*  Ho    = smem + HO_OFF;
    float*  Ht    = smem + HT_OFF;
    float*  Yp    = smem + YP_OFF;
    float*  bias1 = smem + B1_OFF;
    float*  wijb  = smem + WIJB_OFF;

    // one-time preload
    for (int i = tid; i < 208 * 64; i += 256) ws2[i] = g_Wt2[i];
    for (int i = tid; i < 384; i += 256) {
        float b;
        if (i < 192) b = wr_b[i];
        else { int tt = i - 192, g = tt >> 6, u = tt & 63;
               b = wz_b[64 * (g + 1) + u] - wz_b[u]; }
        bias1[i] = b;
    }
    if (tid < 64) wijb[tid] = wij_b[tid];
    for (int i = tid; i < 6144; i += 256) He[i] = 0.0f;   // He,Ho,Ht contiguous
    {   // x-section of As for s=0: cell (2p, 0)
        const float2* Xp0 = g_Xp + ((size_t)((2 * p) * 64 + 0) * 4 + q) * 128;
        if (tid < 128) As[(192 + (tid >> 3)) * RS2 + (tid & 7)] = Xp0[tid];
    }
    __syncthreads();

    const float* wp  = g_Wt1 + (size_t)(kg * 52) * N1 + nl;
    const float* Wb2 = ws2 + (size_t)(kg * 52) * 64 + nl;
    const ulonglong2* Ab = (const ulonglong2*)As + (size_t)(kg * 52) * 5;

    for (int s = 0; s < 128; s++) {
        const int sub = s & 1;
        const int r = s >> 1;
        const int l = 2 * p + sub;
        const int rb = r & 1, rp = rb ^ 1;

        const float *hl_s, *ht_s, *hd_s;
        float* hdst;
        if (sub == 0) { hl_s = He + rp * 1024; ht_s = Ht + rb * 1024;
                        hd_s = Ht + rp * 1024; hdst = He + rb * 1024; }
        else          { hl_s = Ho + rp * 1024; ht_s = He + rb * 1024;
                        hd_s = He + rp * 1024; hdst = Ho + rb * 1024; }

        if (sub == 0 && p > 0) {
            if (tid == 0) {
                const int* fp = &g_flag[(q * 64 + (2 * p - 1)) * 64 + r];
                int v;
                do {
                    asm volatile("ld.acquire.gpu.global.b32 %0, [%1];" : "=r"(v) : "l"(fp));
                    if (!v) __nanosleep(64);
                } while (!v);
            }
            __syncthreads();
        }

        const float* Gtop = g_H + ((size_t)((2 * p - 1) * 64 + r)) * 4096 + b0 * 64;
        float* Htcur = Ht + rb * 1024;

        // ---- build A1 h-rows [k<192]: m-paired {h_top|h_left|h_diag} ----
        {
            const int m0 = 2 * mp_b, m1 = m0 + 1;
#pragma unroll
            for (int c = 0; c < 6; c++) {
                int k = kb_b + 32 * c;
                float v0, v1;
                if (k < 64) {
                    if (sub == 0) {
                        if (p > 0) {
                            v0 = Gtop[m0 * 64 + k]; v1 = Gtop[m1 * 64 + k];
                            Htcur[m0 * 64 + k] = v0; Htcur[m1 * 64 + k] = v1;
                        } else { v0 = 0.0f; v1 = 0.0f; }
                    } else {
                        v0 = ht_s[m0 * 64 + k]; v1 = ht_s[m1 * 64 + k];
                    }
                } else if (k < 128) {
                    int ko = k - 64;
                    v0 = hl_s[m0 * 64 + ko]; v1 = hl_s[m1 * 64 + ko];
                } else {
                    int ko = k - 128;
                    v0 = hd_s[m0 * 64 + ko]; v1 = hd_s[m1 * 64 + ko];
                }
                As[k * RS2 + mp_b] = make_float2(v0, v1);
            }
        }
        // hoisted stage-1 W prologue
        float wA[JT], wB[JT];
        LDW1(wA, 0); LDW1(wB, 1);
        __syncthreads();

        // ---- stage-1 GEMM: acc[j][mp], W from L2 (4-deep), A broadcast ----
        ull acc[JT][8];
#pragma unroll
        for (int j = 0; j < JT; j++)
#pragma unroll
            for (int m = 0; m < 8; m++) acc[j][m] = 0ULL;
        {
            ulonglong2 aA[4], aB[4];
            LDA(aA, 0);
            for (int kk = 0; kk < 52; kk += 2) {
                ull wdA[JT];
#pragma unroll
                for (int j = 0; j < JT; j++) wdA[j] = dup2(wA[j]);
                LDA(aB, kk + 1);
                if (kk + 2 < 52) LDW1(wA, kk + 2);
                FMAB(wdA, aA);
                ull wdB[JT];
#pragma unroll
                for (int j = 0; j < JT; j++) wdB[j] = dup2(wB[j]);
                if (kk + 2 < 52) LDA(aA, kk + 2);
                if (kk + 3 < 52) LDW1(wB, kk + 3);
                FMAB(wdB, aB);
            }
        }
#pragma unroll
        for (int j = 0; j < JT; j++)
#pragma unroll
            for (int m = 0; m < 8; m++)
                Pv[(size_t)kg * 3072 + (j * 8 + m) * 64 + nl] = unpack2(acc[j][m]);
        __syncthreads();

        // ---- reduce1 (fused build-A2): rr -> As = rr*hu ; z-diff -> Yp ----
#pragma unroll
        for (int i = 0; i < 12; i++) {
            int f = tid + 256 * i;
            int nl2 = f & 63, m = (f >> 6) & 7, j = f >> 9;
            int base = (j * 8 + m) * 64 + nl2;
            float2 s0 = Pv[base], s1 = Pv[3072 + base];
            float2 s2 = Pv[6144 + base], s3 = Pv[9216 + base];
            int n = nl2 + 64 * j;
            float b = bias1[n];
            float x0 = ((s0.x + s1.x) + (s2.x + s3.x)) + b;
            float x1 = ((s0.y + s1.y) + (s2.y + s3.y)) + b;
            if (j < 3) {
                x0 = __fdividef(1.0f, 1.0f + __expf(-x0));
                x1 = __fdividef(1.0f, 1.0f + __expf(-x1));
                // A2 k-order: [h_left | h_top | h_diag]
                const float* Hs = (j == 0) ? hl_s : ((j == 1) ? ht_s : hd_s);
                float h0 = Hs[(2 * m) * 64 + nl2];
                float h1 = Hs[(2 * m + 1) * 64 + nl2];
                As[n * RS2 + m] = make_float2(x0 * h0, x1 * h1);
            } else {
                int g = j - 3;
                Yp[g * 1024 + (2 * m) * 64 + nl2] = x0;
                Yp[g * 1024 + (2 * m + 1) * 64 + nl2] = x1;
            }
        }
        // hoisted stage-2 W prologue (smem)
        float w40 = Wb2[0], w41 = Wb2[64], w42 = Wb2[128], w43 = Wb2[192];
        __syncthreads();

        // ---- stage-2 GEMM: A = As, W2 from smem (explicit 4-slot rotation) ----
        ull acc2[8];
#pragma unroll
        for (int m = 0; m < 8; m++) acc2[m] = 0ULL;
#pragma unroll
        for (int kk = 0; kk < 52; kk += 4) {
            G2STEP(w40, kk)
            G2STEP(w41, kk + 1)
            G2STEP(w42, kk + 2)
            G2STEP(w43, kk + 3)
        }
#pragma unroll
        for (int m = 0; m < 8; m++)
            Pv[(size_t)kg * 512 + m * 64 + nl] = unpack2(acc2[m]);
        __syncthreads();

        // ---- epilogue: reduce + tanh + gates (no max-shift) + H update ----
        {
            float* Gout = g_H + ((size_t)(l * 64 + r)) * 4096 + b0 * 64;
            const bool last = (l == 63) && (r == 63);
#pragma unroll
            for (int i = 0; i < 2; i++) {
                int f = tid + 256 * i;
                int u = f & 63, m = f >> 6;
                int base = m * 64 + u;
                float2 s0 = Pv[base], s1 = Pv[512 + base];
                float2 s2 = Pv[1024 + base], s3 = Pv[1536 + base];
                float wb = wijb[u];
                float av[2] = {((s0.x + s1.x) + (s2.x + s3.x)) + wb,
                               ((s0.y + s1.y) + (s2.y + s3.y)) + wb};
#pragma unroll
                for (int h2 = 0; h2 < 2; h2++) {
                    int mm = 2 * m + h2;
                    float hnew = fast_tanh(av[h2]);
                    float z1 = Yp[mm * 64 + u];
                    float z2 = Yp[1024 + mm * 64 + u];
                    float z3 = Yp[2048 + mm * 64 + u];
                    float e1 = __expf(z1), e2 = __expf(z2), e3 = __expf(z3);
                    float inv = __fdividef(1.0f, 1.0f + e1 + e2 + e3);
                    float h = (hnew + e1 * hl_s[mm * 64 + u] +
                               e2 * ht_s[mm * 64 + u] + e3 * hd_s[mm * 64 + u]) * inv;
                    hdst[mm * 64 + u] = h;
                    if (sub == 1) Gout[mm * 64 + u] = h;
                    if (last) out[(b0 + mm) * 64 + u] = h;
                }
            }
            if (s < 127 && tid < 128) {   // x-section of As for next cell
                int s2_ = s + 1;
                int r2 = s2_ >> 1, l2 = 2 * p + (s2_ & 1);
                const float2* Xpn = g_Xp + ((size_t)(l2 * 64 + r2) * 4 + q) * 128;
                As[(192 + (tid >> 3)) * RS2 + (tid & 7)] = Xpn[tid];
            }
        }
        __syncthreads();

        if (sub == 1 && tid == 0) {
            int* fp = &g_flag[(q * 64 + l) * 64 + r];
            asm volatile("st.release.gpu.global.b32 [%0], %1;" :: "l"(fp), "r"(1) : "memory");
        }
    }
}

extern "C" void kernel_launch(void* const* d_in, const int* in_sizes, int n_in,
                              void* d_out, int out_size)
{
    const float* inputs = (const float*)d_in[0];
    const float* wr_w   = (const float*)d_in[1];
    const float* wr_b   = (const float*)d_in[2];
    const float* wz_w   = (const float*)d_in[3];
    const float* wz_b   = (const float*)d_in[4];
    const float* wij_w  = (const float*)d_in[5];
    const float* wij_b  = (const float*)d_in[6];
    const float* U_w    = (const float*)d_in[7];
    float* out = (float*)d_out;

    cudaFuncSetAttribute(pipeline_kernel, cudaFuncAttributeMaxDynamicSharedMemorySize, SMEM_BYTES);

    init_kernel<<<512, 256>>>(inputs, wr_w, wz_w, U_w, wij_w);
    pipeline_kernel<<<128, 256, SMEM_BYTES>>>(wr_b, wz_b, wij_b, out);
}